// round 16
// baseline (speedup 1.0000x reference)
#include <cuda_runtime.h>
#include <cuda_bf16.h>
#include <cstdint>

#define Bn 8
#define CN 64
#define CL 32
#define CH 128
#define Himg 256
#define HMimg 512
#define SLOPE 0.2f
#define GAINF 1.4142135623730951f
#define EPSV 1e-5f

// uint4 fragment tables: entry e -> lane=e&31, ntp=(e>>5)&7, kt=e>>8
// words h=0..3: nt=2*ntp+(h>>1), pair=h&1
__device__ uint4 g_fB1q[512];    // kt<2
__device__ uint4 g_fB2q[2048];   // kt<8
// layout: [b][chgroup(8)][px(65536)][4ch] bf16  (one uint2 per (px,group))
__device__ __nv_bfloat16 g_v[(size_t)Bn * 8 * 65536 * 4];
__device__ float g_mu[512];
__device__ float g_rstd[512];

static __device__ __forceinline__ unsigned pack_bf16x2(float a, float b) {
    __nv_bfloat162 t = __floats2bfloat162_rn(a, b);
    return *reinterpret_cast<unsigned*>(&t);
}

// ---------------- FIR downsample (vertical-first) + fused stats + weight tables ---------
// grid (8, 16, 68):
//   z <  64 : FIR block, 16x32 out-tile of (b = z>>3, chgroup = z&7)
//   z >= 64 : instance-norm stats block for plane bc = (z-64)*128 + y*8 + x
// Blocks (z==0, y==0) also build the GEMM weight-fragment tables.
__global__ void __launch_bounds__(256, 4)
fir_kernel(const float* __restrict__ hm, const float* __restrict__ F,
           const float* __restrict__ w_shared,
           const float* __restrict__ w_gamma,
           const float* __restrict__ w_beta,
           const float* __restrict__ x) {
    const int tid = threadIdx.x;
    const int bz = blockIdx.z;

    // ================= stats blocks =================
    if (bz >= 64) {
        int bc = (bz - 64) * 128 + blockIdx.y * 8 + blockIdx.x;
        const float4* xp = reinterpret_cast<const float4*>(x + (size_t)bc * 65536);
        float s = 0.f, q = 0.f;
#pragma unroll 8
        for (int i = tid; i < 16384; i += 256) {
            float4 v = __ldg(&xp[i]);
            s += (v.x + v.y) + (v.z + v.w);
            q += v.x * v.x + v.y * v.y + v.z * v.z + v.w * v.w;
        }
#pragma unroll
        for (int o = 16; o > 0; o >>= 1) {
            s += __shfl_down_sync(0xffffffffu, s, o);
            q += __shfl_down_sync(0xffffffffu, q, o);
        }
        __shared__ float ws[8], wq[8];
        int w = tid >> 5;
        if ((tid & 31) == 0) { ws[w] = s; wq[w] = q; }
        __syncthreads();
        if (tid == 0) {
            float S = 0.f, Q = 0.f;
#pragma unroll
            for (int i = 0; i < 8; i++) { S += ws[i]; Q += wq[i]; }
            float mu = S * (1.f / 65536.f);
            float var = Q * (1.f / 65536.f) - mu * mu;
            g_mu[bc] = mu;
            g_rstd[bc] = rsqrtf(var + EPSV);
        }
        return;
    }

    // ================= FIR blocks =================
    __shared__ float vint[4 * 16 * 100];   // 25600 B, row pad 100 (bank-shift 4)
    __shared__ float sres[4 * 16 * 36];    //  9216 B, row pad 36

    const int x0 = blockIdx.x * 32;
    const int y0 = blockIdx.y * 16;
    const int lane = tid & 31;
    const int wid = tid >> 5;

    // ---- weight-fragment table build (8 blocks do 1/8 each; gemm runs later) ----
    if (bz == 0 && blockIdx.y == 0) {
        int slice = blockIdx.x;
        if (tid < 64) {
            int e = slice * 64 + tid;       // uint4 entry of g_fB1q
            int ln = e & 31, ntp = (e >> 5) & 7, kt = e >> 8;
            unsigned v[4];
#pragma unroll
            for (int h = 0; h < 4; h++) {
                int nt = ntp * 2 + (h >> 1);
                int pair = h & 1;
                int n = nt * 8 + (ln >> 2);
                int k = kt * 16 + (ln & 3) * 2 + pair * 8;
                v[h] = pack_bf16x2(__ldg(&w_shared[n * CL + k]),
                                   __ldg(&w_shared[n * CL + k + 1]));
            }
            g_fB1q[e] = make_uint4(v[0], v[1], v[2], v[3]);
        }
        {
            int e = slice * 256 + tid;      // uint4 entry of g_fB2q
            int ln = e & 31, ntp = (e >> 5) & 7, kt = e >> 8;
            unsigned v[4];
#pragma unroll
            for (int h = 0; h < 4; h++) {
                int nt = ntp * 2 + (h >> 1);
                int pair = h & 1;
                int n = nt * 8 + (ln >> 2);
                int k = kt * 16 + (ln & 3) * 2 + pair * 8;
                float a0, a1;
                if (n < 64) { a0 = __ldg(&w_gamma[n * CH + k]); a1 = __ldg(&w_gamma[n * CH + k + 1]); }
                else        { a0 = __ldg(&w_beta[(n - 64) * CH + k]); a1 = __ldg(&w_beta[(n - 64) * CH + k + 1]); }
                v[h] = pack_bf16x2(a0, a1);
            }
            g_fB2q[e] = make_uint4(v[0], v[1], v[2], v[3]);
        }
    }

    // flipped 1D filter from rank-1 F
    float a[12];
    {
        float rs = rsqrtf(__ldg(&F[5 * 12 + 5]));
#pragma unroll
        for (int j = 0; j < 12; j++) a[j] = __ldg(&F[(11 - j) * 12 + 5]) * rs;
    }

    const float* hmb = hm + ((size_t)((bz >> 3) * CL + (bz & 7) * 4)) * (HMimg * HMimg);
    const bool interior = (blockIdx.x >= 1) & (blockIdx.x <= 6) &
                          (blockIdx.y >= 1) & (blockIdx.y <= 14);

    // ---- phase 1: vertical FIR straight from gmem, lane = column (perfect coalescing)
    for (int t = wid; t < 12; t += 8) {
        int c = t / 3;
        int ck = t - c * 3;
        int gc = 2 * x0 - 8 + ck * 32 + lane;
        const float* cp = hmb + (size_t)c * (HMimg * HMimg) + gc;
        const int gr0 = 2 * y0 - 5;

        float acc[16];
#pragma unroll
        for (int o = 0; o < 16; o++) acc[o] = 0.f;

        if (interior) {
            const float* rp = cp + (size_t)gr0 * HMimg;
#pragma unroll
            for (int r = 0; r < 42; r++) {
                float v = __ldg(rp);
                rp += HMimg;
#pragma unroll
                for (int o = 0; o < 16; o++) {
                    int j = r - 2 * o;
                    if (j >= 0 && j < 12) acc[o] += v * a[j];
                }
            }
        } else {
            bool cok = ((unsigned)gc < 512u);
#pragma unroll
            for (int r = 0; r < 42; r++) {
                int gr = gr0 + r;
                float v = (cok && (unsigned)gr < 512u) ? __ldg(cp + (size_t)gr * HMimg) : 0.f;
#pragma unroll
                for (int o = 0; o < 16; o++) {
                    int j = r - 2 * o;
                    if (j >= 0 && j < 12) acc[o] += v * a[j];
                }
            }
        }
#pragma unroll
        for (int o = 0; o < 16; o++)
            vint[(c * 16 + o) * 100 + ck * 32 + lane] = acc[o];
    }
    __syncthreads();

    // ---- phase 2: horizontal FIR (stride 2) from vint, 4 out-cols per task ----
    for (int t = tid; t < 512; t += 256) {
        int r = t & 15;
        int oq = (t >> 4) & 7;
        int c = t >> 7;
        const float4* wp = reinterpret_cast<const float4*>(&vint[(c * 16 + r) * 100 + 8 * oq]);
        float w[24];
#pragma unroll
        for (int k = 0; k < 6; k++) {
            float4 v = wp[k];
            w[k * 4 + 0] = v.x; w[k * 4 + 1] = v.y; w[k * 4 + 2] = v.z; w[k * 4 + 3] = v.w;
        }
        float o[4];
#pragma unroll
        for (int q = 0; q < 4; q++) {
            float a0 = 0.f, a1 = 0.f;
#pragma unroll
            for (int j = 0; j < 6; j++) {
                a0 += w[2 * q + 3 + j] * a[j];
                a1 += w[2 * q + 9 + j] * a[j + 6];
            }
            o[q] = a0 + a1;
        }
        *reinterpret_cast<float4*>(&sres[(c * 16 + r) * 36 + 4 * oq]) =
            make_float4(o[0], o[1], o[2], o[3]);
    }
    __syncthreads();

    // ---- phase 3: pack 4 channels per pixel, coalesced store ----
    for (int p = tid; p < 512; p += 256) {
        int orow = p >> 5;
        int ox = p & 31;
        uint2 val;
        val.x = pack_bf16x2(sres[(0 * 16 + orow) * 36 + ox], sres[(1 * 16 + orow) * 36 + ox]);
        val.y = pack_bf16x2(sres[(2 * 16 + orow) * 36 + ox], sres[(3 * 16 + orow) * 36 + ox]);
        size_t px = (size_t)(y0 + orow) * Himg + (x0 + ox);
        reinterpret_cast<uint2*>(g_v)[((size_t)bz << 16) + px] = val;
    }
}

// ---------------- mma helpers ----------------
static __device__ __forceinline__ void ldsm4(unsigned r[4], unsigned addr) {
    asm volatile("ldmatrix.sync.aligned.m8n8.x4.shared.b16 {%0,%1,%2,%3}, [%4];"
                 : "=r"(r[0]), "=r"(r[1]), "=r"(r[2]), "=r"(r[3])
                 : "r"(addr) : "memory");
}
static __device__ __forceinline__ void mma_bf16(float c[4], const unsigned a[4],
                                                unsigned b0, unsigned b1) {
    asm("mma.sync.aligned.m16n8k16.row.col.f32.bf16.bf16.f32 "
        "{%0,%1,%2,%3}, {%4,%5,%6,%7}, {%8,%9}, {%0,%1,%2,%3};"
        : "+f"(c[0]), "+f"(c[1]), "+f"(c[2]), "+f"(c[3])
        : "r"(a[0]), "r"(a[1]), "r"(a[2]), "r"(a[3]), "r"(b0), "r"(b1));
}

// -------- GEMM1 + GEMM2 + fused instance-norm apply -> out (register-chained) --------
// grid (512, 8): 128 consecutive px per block. 8 warps, each owns M=16 rows, full N.
// Epilogue transposes gamma/beta through smem for fully-coalesced x/out streaming.
__global__ void __launch_bounds__(256, 2)
gemm_kernel(const float* __restrict__ b_shared,
            const float* __restrict__ b_gamma,
            const float* __restrict__ b_beta,
            const float* __restrict__ x,
            float* __restrict__ out) {
    __shared__ __nv_bfloat16 sv[128 * 40];       // 10240 B
    __shared__ unsigned sh_gb[64 * 132];         // 33792 B, packed (gamma,beta) bf16x2

    const int tid = threadIdx.x;
    const int lane = tid & 31;
    const int warp = tid >> 5;           // 0..7 -> rows warp*16 .. warp*16+15
    const int b = blockIdx.y;
    const int px0 = blockIdx.x * 128;

    // stage A: v from [b][g][px][4] layout -> sv[128][40], uint4 loads (2 px each)
    {
        const uint4* src = reinterpret_cast<const uint4*>(g_v) + (((size_t)b * 8) << 15) + (px0 >> 1);
        for (int e = tid; e < 512; e += 256) {
            int g = e >> 6, pxp = e & 63;
            uint4 v = __ldg(&src[((size_t)g << 15) + pxp]);
            int px = pxp * 2;
            *reinterpret_cast<uint2*>(&sv[px * 40 + g * 4]) = make_uint2(v.x, v.y);
            *reinterpret_cast<uint2*>(&sv[(px + 1) * 40 + g * 4]) = make_uint2(v.z, v.w);
        }
    }
    __syncthreads();

    const int gid = lane >> 2, tig = lane & 3;
    const int r16 = lane & 15;
    const int khalf = (lane >> 4) << 3;
    unsigned sbase = (unsigned)__cvta_generic_to_shared(sv);

    unsigned A1[2][4];
    ldsm4(A1[0], sbase + ((warp * 16 + r16) * 40 + khalf) * 2);
    ldsm4(A1[1], sbase + ((warp * 16 + r16) * 40 + khalf + 16) * 2);

    // ---- GEMM1: M16 N128 K32 ----
    float acc1[16][4];
#pragma unroll
    for (int nt = 0; nt < 16; nt++)
#pragma unroll
        for (int i = 0; i < 4; i++) acc1[nt][i] = 0.f;
#pragma unroll
    for (int kt = 0; kt < 2; kt++)
#pragma unroll
        for (int ntp = 0; ntp < 8; ntp++) {
            uint4 q = __ldg(&g_fB1q[(kt * 8 + ntp) * 32 + lane]);
            mma_bf16(acc1[2 * ntp], A1[kt], q.x, q.y);
            mma_bf16(acc1[2 * ntp + 1], A1[kt], q.z, q.w);
        }

    // ---- bias + lrelu*gain, pack acc1 into GEMM2 A-fragments (registers) ----
    unsigned A2[8][4];
#pragma unroll
    for (int nt = 0; nt < 16; nt++) {
        int c0 = nt * 8 + tig * 2;
        float bb0 = __ldg(&b_shared[c0]), bb1 = __ldg(&b_shared[c0 + 1]);
        float v00 = acc1[nt][0] + bb0, v01 = acc1[nt][1] + bb1;
        float v10 = acc1[nt][2] + bb0, v11 = acc1[nt][3] + bb1;
        v00 = (v00 >= 0.f ? v00 : v00 * SLOPE) * GAINF;
        v01 = (v01 >= 0.f ? v01 : v01 * SLOPE) * GAINF;
        v10 = (v10 >= 0.f ? v10 : v10 * SLOPE) * GAINF;
        v11 = (v11 >= 0.f ? v11 : v11 * SLOPE) * GAINF;
        int kt2 = nt >> 1;
        int off = (nt & 1) * 2;
        A2[kt2][off + 0] = pack_bf16x2(v00, v01);
        A2[kt2][off + 1] = pack_bf16x2(v10, v11);
    }

    // ---- GEMM2: M16 N128 K128 ----
    float acc2[16][4];
#pragma unroll
    for (int nt = 0; nt < 16; nt++)
#pragma unroll
        for (int i = 0; i < 4; i++) acc2[nt][i] = 0.f;
#pragma unroll
    for (int kt = 0; kt < 8; kt++)
#pragma unroll
        for (int ntp = 0; ntp < 8; ntp++) {
            uint4 q = __ldg(&g_fB2q[(kt * 8 + ntp) * 32 + lane]);
            mma_bf16(acc2[2 * ntp], A2[kt], q.x, q.y);
            mma_bf16(acc2[2 * ntp + 1], A2[kt], q.z, q.w);
        }

    // ---- transpose gamma/beta (+bias) into sh_gb[ch][132] (conflict-free STS) ----
    {
        const int pxl = warp * 16 + gid;   // local px 0..127
#pragma unroll
        for (int nt = 0; nt < 8; nt++) {
            int c = nt * 8 + tig * 2;
            float bg0 = __ldg(&b_gamma[c]), bg1 = __ldg(&b_gamma[c + 1]);
            float bt0 = __ldg(&b_beta[c]),  bt1 = __ldg(&b_beta[c + 1]);
            sh_gb[c * 132 + pxl]           = pack_bf16x2(acc2[nt][0] + bg0, acc2[nt + 8][0] + bt0);
            sh_gb[(c + 1) * 132 + pxl]     = pack_bf16x2(acc2[nt][1] + bg1, acc2[nt + 8][1] + bt1);
            sh_gb[c * 132 + pxl + 8]       = pack_bf16x2(acc2[nt][2] + bg0, acc2[nt + 8][2] + bt0);
            sh_gb[(c + 1) * 132 + pxl + 8] = pack_bf16x2(acc2[nt][3] + bg1, acc2[nt + 8][3] + bt1);
        }
    }
    __syncthreads();

    // ---- streaming epilogue: fully coalesced x read / out write, one channel per warp-iter ----
    {
        const float* xb = x + (((size_t)b * CN) << 16) + px0;
        float* ob = out + (((size_t)b * CN) << 16) + px0;
#pragma unroll
        for (int k = tid; k < 2048; k += 256) {
            int ch = k >> 5;           // warp covers one channel, 32 float4 = 128 px
            int pxq = k & 31;
            uint4 g = *reinterpret_cast<const uint4*>(&sh_gb[ch * 132 + 4 * pxq]);
            const float4 xv = __ldg(reinterpret_cast<const float4*>(xb + ((size_t)ch << 16)) + pxq);
            float mu = __ldg(&g_mu[b * CN + ch]);
            float rs = __ldg(&g_rstd[b * CN + ch]);
            float4 r;
            {
                __nv_bfloat162 p = *reinterpret_cast<__nv_bfloat162*>(&g.x);
                float xn = (xv.x - mu) * rs;
                r.x = xn * (1.f + __bfloat162float(p.x)) + __bfloat162float(p.y) + 0.1f * xv.x;
            }
            {
                __nv_bfloat162 p = *reinterpret_cast<__nv_bfloat162*>(&g.y);
                float xn = (xv.y - mu) * rs;
                r.y = xn * (1.f + __bfloat162float(p.x)) + __bfloat162float(p.y) + 0.1f * xv.y;
            }
            {
                __nv_bfloat162 p = *reinterpret_cast<__nv_bfloat162*>(&g.z);
                float xn = (xv.z - mu) * rs;
                r.z = xn * (1.f + __bfloat162float(p.x)) + __bfloat162float(p.y) + 0.1f * xv.z;
            }
            {
                __nv_bfloat162 p = *reinterpret_cast<__nv_bfloat162*>(&g.w);
                float xn = (xv.w - mu) * rs;
                r.w = xn * (1.f + __bfloat162float(p.x)) + __bfloat162float(p.y) + 0.1f * xv.w;
            }
            *(reinterpret_cast<float4*>(ob + ((size_t)ch << 16)) + pxq) = r;
        }
    }
}

extern "C" void kernel_launch(void* const* d_in, const int* in_sizes, int n_in,
                              void* d_out, int out_size) {
    (void)in_sizes; (void)n_in; (void)out_size;
    const float* x        = (const float*)d_in[0];
    const float* hm       = (const float*)d_in[1];
    const float* F        = (const float*)d_in[2];
    const float* w_shared = (const float*)d_in[3];
    const float* b_shared = (const float*)d_in[4];
    const float* w_gamma  = (const float*)d_in[5];
    const float* b_gamma  = (const float*)d_in[6];
    const float* w_beta   = (const float*)d_in[7];
    const float* b_beta   = (const float*)d_in[8];
    float* out = (float*)d_out;

    dim3 fgrid(8, 16, 68);   // z<64: FIR blocks; z>=64: stats blocks
    fir_kernel<<<fgrid, 256>>>(hm, F, w_shared, w_gamma, w_beta, x);
    dim3 ggrid(512, 8);
    gemm_kernel<<<ggrid, 256>>>(b_shared, b_gamma, b_beta, x, out);
}

// round 17
// speedup vs baseline: 1.0097x; 1.0097x over previous
#include <cuda_runtime.h>
#include <cuda_bf16.h>
#include <cstdint>

#define Bn 8
#define CN 64
#define CL 32
#define CH 128
#define Himg 256
#define HMimg 512
#define SLOPE 0.2f
#define GAINF 1.4142135623730951f
#define EPSV 1e-5f

// uint4 fragment tables: entry e -> lane=e&31, ntp=(e>>5)&7, kt=e>>8
// words h=0..3: nt=2*ntp+(h>>1), pair=h&1
__device__ uint4 g_fB1q[512];    // kt<2
__device__ uint4 g_fB2q[2048];   // kt<8
// layout: [b][chgroup(8)][px(65536)][4ch] bf16  (one uint2 per (px,group))
__device__ __nv_bfloat16 g_v[(size_t)Bn * 8 * 65536 * 4];
__device__ float g_mu[512];
__device__ float g_rstd[512];

static __device__ __forceinline__ unsigned pack_bf16x2(float a, float b) {
    __nv_bfloat162 t = __floats2bfloat162_rn(a, b);
    return *reinterpret_cast<unsigned*>(&t);
}

// ---------------- FIR downsample (vertical-first) + fused stats + weight tables ---------
// grid (8, 16, 68):
//   z <  64 : FIR block, 16x32 out-tile of (b = z>>3, chgroup = z&7)
//   z >= 64 : instance-norm stats block for plane bc = (z-64)*128 + y*8 + x
// Blocks (z==0, y==0) also build the GEMM weight-fragment tables.
__global__ void __launch_bounds__(256, 4)
fir_kernel(const float* __restrict__ hm, const float* __restrict__ F,
           const float* __restrict__ w_shared,
           const float* __restrict__ w_gamma,
           const float* __restrict__ w_beta,
           const float* __restrict__ x) {
    const int tid = threadIdx.x;
    const int bz = blockIdx.z;

    // ================= stats blocks =================
    if (bz >= 64) {
        int bc = (bz - 64) * 128 + blockIdx.y * 8 + blockIdx.x;
        const float4* xp = reinterpret_cast<const float4*>(x + (size_t)bc * 65536);
        float s = 0.f, q = 0.f;
#pragma unroll 8
        for (int i = tid; i < 16384; i += 256) {
            float4 v = __ldg(&xp[i]);
            s += (v.x + v.y) + (v.z + v.w);
            q += v.x * v.x + v.y * v.y + v.z * v.z + v.w * v.w;
        }
#pragma unroll
        for (int o = 16; o > 0; o >>= 1) {
            s += __shfl_down_sync(0xffffffffu, s, o);
            q += __shfl_down_sync(0xffffffffu, q, o);
        }
        __shared__ float ws[8], wq[8];
        int w = tid >> 5;
        if ((tid & 31) == 0) { ws[w] = s; wq[w] = q; }
        __syncthreads();
        if (tid == 0) {
            float S = 0.f, Q = 0.f;
#pragma unroll
            for (int i = 0; i < 8; i++) { S += ws[i]; Q += wq[i]; }
            float mu = S * (1.f / 65536.f);
            float var = Q * (1.f / 65536.f) - mu * mu;
            g_mu[bc] = mu;
            g_rstd[bc] = rsqrtf(var + EPSV);
        }
        return;
    }

    // ================= FIR blocks =================
    __shared__ float vint[4 * 16 * 100];   // 25600 B, row pad 100 (bank-shift 4)
    __shared__ float sres[4 * 16 * 36];    //  9216 B, row pad 36

    const int x0 = blockIdx.x * 32;
    const int y0 = blockIdx.y * 16;
    const int lane = tid & 31;
    const int wid = tid >> 5;

    // ---- weight-fragment table build (8 blocks do 1/8 each; gemm runs later) ----
    if (bz == 0 && blockIdx.y == 0) {
        int slice = blockIdx.x;
        if (tid < 64) {
            int e = slice * 64 + tid;       // uint4 entry of g_fB1q
            int ln = e & 31, ntp = (e >> 5) & 7, kt = e >> 8;
            unsigned v[4];
#pragma unroll
            for (int h = 0; h < 4; h++) {
                int nt = ntp * 2 + (h >> 1);
                int pair = h & 1;
                int n = nt * 8 + (ln >> 2);
                int k = kt * 16 + (ln & 3) * 2 + pair * 8;
                v[h] = pack_bf16x2(__ldg(&w_shared[n * CL + k]),
                                   __ldg(&w_shared[n * CL + k + 1]));
            }
            g_fB1q[e] = make_uint4(v[0], v[1], v[2], v[3]);
        }
        {
            int e = slice * 256 + tid;      // uint4 entry of g_fB2q
            int ln = e & 31, ntp = (e >> 5) & 7, kt = e >> 8;
            unsigned v[4];
#pragma unroll
            for (int h = 0; h < 4; h++) {
                int nt = ntp * 2 + (h >> 1);
                int pair = h & 1;
                int n = nt * 8 + (ln >> 2);
                int k = kt * 16 + (ln & 3) * 2 + pair * 8;
                float a0, a1;
                if (n < 64) { a0 = __ldg(&w_gamma[n * CH + k]); a1 = __ldg(&w_gamma[n * CH + k + 1]); }
                else        { a0 = __ldg(&w_beta[(n - 64) * CH + k]); a1 = __ldg(&w_beta[(n - 64) * CH + k + 1]); }
                v[h] = pack_bf16x2(a0, a1);
            }
            g_fB2q[e] = make_uint4(v[0], v[1], v[2], v[3]);
        }
    }

    // flipped 1D filter from rank-1 F
    float a[12];
    {
        float rs = rsqrtf(__ldg(&F[5 * 12 + 5]));
#pragma unroll
        for (int j = 0; j < 12; j++) a[j] = __ldg(&F[(11 - j) * 12 + 5]) * rs;
    }

    const float* hmb = hm + ((size_t)((bz >> 3) * CL + (bz & 7) * 4)) * (HMimg * HMimg);
    const bool interior = (blockIdx.x >= 1) & (blockIdx.x <= 6) &
                          (blockIdx.y >= 1) & (blockIdx.y <= 14);

    // ---- phase 1: vertical FIR straight from gmem, lane = column (perfect coalescing)
    for (int t = wid; t < 12; t += 8) {
        int c = t / 3;
        int ck = t - c * 3;
        int gc = 2 * x0 - 8 + ck * 32 + lane;
        const float* cp = hmb + (size_t)c * (HMimg * HMimg) + gc;
        const int gr0 = 2 * y0 - 5;

        float acc[16];
#pragma unroll
        for (int o = 0; o < 16; o++) acc[o] = 0.f;

        if (interior) {
            const float* rp = cp + (size_t)gr0 * HMimg;
#pragma unroll
            for (int r = 0; r < 42; r++) {
                float v = __ldg(rp);
                rp += HMimg;
#pragma unroll
                for (int o = 0; o < 16; o++) {
                    int j = r - 2 * o;
                    if (j >= 0 && j < 12) acc[o] += v * a[j];
                }
            }
        } else {
            bool cok = ((unsigned)gc < 512u);
#pragma unroll
            for (int r = 0; r < 42; r++) {
                int gr = gr0 + r;
                float v = (cok && (unsigned)gr < 512u) ? __ldg(cp + (size_t)gr * HMimg) : 0.f;
#pragma unroll
                for (int o = 0; o < 16; o++) {
                    int j = r - 2 * o;
                    if (j >= 0 && j < 12) acc[o] += v * a[j];
                }
            }
        }
#pragma unroll
        for (int o = 0; o < 16; o++)
            vint[(c * 16 + o) * 100 + ck * 32 + lane] = acc[o];
    }
    __syncthreads();

    // ---- phase 2: horizontal FIR (stride 2) from vint, 4 out-cols per task ----
    for (int t = tid; t < 512; t += 256) {
        int r = t & 15;
        int oq = (t >> 4) & 7;
        int c = t >> 7;
        const float4* wp = reinterpret_cast<const float4*>(&vint[(c * 16 + r) * 100 + 8 * oq]);
        float w[24];
#pragma unroll
        for (int k = 0; k < 6; k++) {
            float4 v = wp[k];
            w[k * 4 + 0] = v.x; w[k * 4 + 1] = v.y; w[k * 4 + 2] = v.z; w[k * 4 + 3] = v.w;
        }
        float o[4];
#pragma unroll
        for (int q = 0; q < 4; q++) {
            float a0 = 0.f, a1 = 0.f;
#pragma unroll
            for (int j = 0; j < 6; j++) {
                a0 += w[2 * q + 3 + j] * a[j];
                a1 += w[2 * q + 9 + j] * a[j + 6];
            }
            o[q] = a0 + a1;
        }
        *reinterpret_cast<float4*>(&sres[(c * 16 + r) * 36 + 4 * oq]) =
            make_float4(o[0], o[1], o[2], o[3]);
    }
    __syncthreads();

    // ---- phase 3: pack 4 channels per pixel, coalesced store ----
    for (int p = tid; p < 512; p += 256) {
        int orow = p >> 5;
        int ox = p & 31;
        uint2 val;
        val.x = pack_bf16x2(sres[(0 * 16 + orow) * 36 + ox], sres[(1 * 16 + orow) * 36 + ox]);
        val.y = pack_bf16x2(sres[(2 * 16 + orow) * 36 + ox], sres[(3 * 16 + orow) * 36 + ox]);
        size_t px = (size_t)(y0 + orow) * Himg + (x0 + ox);
        reinterpret_cast<uint2*>(g_v)[((size_t)bz << 16) + px] = val;
    }
}

// ---------------- mma helpers ----------------
static __device__ __forceinline__ void ldsm4(unsigned r[4], unsigned addr) {
    asm volatile("ldmatrix.sync.aligned.m8n8.x4.shared.b16 {%0,%1,%2,%3}, [%4];"
                 : "=r"(r[0]), "=r"(r[1]), "=r"(r[2]), "=r"(r[3])
                 : "r"(addr) : "memory");
}
static __device__ __forceinline__ void mma_bf16(float c[4], const unsigned a[4],
                                                unsigned b0, unsigned b1) {
    asm("mma.sync.aligned.m16n8k16.row.col.f32.bf16.bf16.f32 "
        "{%0,%1,%2,%3}, {%4,%5,%6,%7}, {%8,%9}, {%0,%1,%2,%3};"
        : "+f"(c[0]), "+f"(c[1]), "+f"(c[2]), "+f"(c[3])
        : "r"(a[0]), "r"(a[1]), "r"(a[2]), "r"(a[3]), "r"(b0), "r"(b1));
}

// -------- GEMM1 + GEMM2 + fused instance-norm apply -> out (register-chained) --------
// grid (512, 8): 128 consecutive px per block. 8 warps, each owns M=16 rows, full N.
// Epilogue transposes gamma/beta through smem for fully-coalesced x/out streaming.
__global__ void __launch_bounds__(256, 2)
gemm_kernel(const float* __restrict__ b_shared,
            const float* __restrict__ b_gamma,
            const float* __restrict__ b_beta,
            const float* __restrict__ x,
            float* __restrict__ out) {
    __shared__ __nv_bfloat16 sv[128 * 40];       // 10240 B
    __shared__ unsigned sh_gb[64 * 132];         // 33792 B, packed (gamma,beta) bf16x2

    const int tid = threadIdx.x;
    const int lane = tid & 31;
    const int warp = tid >> 5;           // 0..7 -> rows warp*16 .. warp*16+15
    const int b = blockIdx.y;
    const int px0 = blockIdx.x * 128;

    // stage A: v from [b][g][px][4] layout -> sv[128][40], uint4 loads (2 px each)
    {
        const uint4* src = reinterpret_cast<const uint4*>(g_v) + (((size_t)b * 8) << 15) + (px0 >> 1);
        for (int e = tid; e < 512; e += 256) {
            int g = e >> 6, pxp = e & 63;
            uint4 v = __ldg(&src[((size_t)g << 15) + pxp]);
            int px = pxp * 2;
            *reinterpret_cast<uint2*>(&sv[px * 40 + g * 4]) = make_uint2(v.x, v.y);
            *reinterpret_cast<uint2*>(&sv[(px + 1) * 40 + g * 4]) = make_uint2(v.z, v.w);
        }
    }
    __syncthreads();

    const int gid = lane >> 2, tig = lane & 3;
    const int r16 = lane & 15;
    const int khalf = (lane >> 4) << 3;
    unsigned sbase = (unsigned)__cvta_generic_to_shared(sv);

    unsigned A1[2][4];
    ldsm4(A1[0], sbase + ((warp * 16 + r16) * 40 + khalf) * 2);
    ldsm4(A1[1], sbase + ((warp * 16 + r16) * 40 + khalf + 16) * 2);

    // ---- GEMM1: M16 N128 K32 ----
    float acc1[16][4];
#pragma unroll
    for (int nt = 0; nt < 16; nt++)
#pragma unroll
        for (int i = 0; i < 4; i++) acc1[nt][i] = 0.f;
#pragma unroll
    for (int kt = 0; kt < 2; kt++)
#pragma unroll
        for (int ntp = 0; ntp < 8; ntp++) {
            uint4 q = __ldg(&g_fB1q[(kt * 8 + ntp) * 32 + lane]);
            mma_bf16(acc1[2 * ntp], A1[kt], q.x, q.y);
            mma_bf16(acc1[2 * ntp + 1], A1[kt], q.z, q.w);
        }

    // ---- bias + lrelu*gain, pack acc1 into GEMM2 A-fragments (registers) ----
    unsigned A2[8][4];
#pragma unroll
    for (int nt = 0; nt < 16; nt++) {
        int c0 = nt * 8 + tig * 2;
        float bb0 = __ldg(&b_shared[c0]), bb1 = __ldg(&b_shared[c0 + 1]);
        float v00 = acc1[nt][0] + bb0, v01 = acc1[nt][1] + bb1;
        float v10 = acc1[nt][2] + bb0, v11 = acc1[nt][3] + bb1;
        v00 = (v00 >= 0.f ? v00 : v00 * SLOPE) * GAINF;
        v01 = (v01 >= 0.f ? v01 : v01 * SLOPE) * GAINF;
        v10 = (v10 >= 0.f ? v10 : v10 * SLOPE) * GAINF;
        v11 = (v11 >= 0.f ? v11 : v11 * SLOPE) * GAINF;
        int kt2 = nt >> 1;
        int off = (nt & 1) * 2;
        A2[kt2][off + 0] = pack_bf16x2(v00, v01);
        A2[kt2][off + 1] = pack_bf16x2(v10, v11);
    }

    // ---- GEMM2: M16 N128 K128 ----
    float acc2[16][4];
#pragma unroll
    for (int nt = 0; nt < 16; nt++)
#pragma unroll
        for (int i = 0; i < 4; i++) acc2[nt][i] = 0.f;
#pragma unroll
    for (int kt = 0; kt < 8; kt++)
#pragma unroll
        for (int ntp = 0; ntp < 8; ntp++) {
            uint4 q = __ldg(&g_fB2q[(kt * 8 + ntp) * 32 + lane]);
            mma_bf16(acc2[2 * ntp], A2[kt], q.x, q.y);
            mma_bf16(acc2[2 * ntp + 1], A2[kt], q.z, q.w);
        }

    // ---- transpose gamma/beta (+bias) into sh_gb[ch][132] (conflict-free STS) ----
    {
        const int pxl = warp * 16 + gid;   // local px 0..127
#pragma unroll
        for (int nt = 0; nt < 8; nt++) {
            int c = nt * 8 + tig * 2;
            float bg0 = __ldg(&b_gamma[c]), bg1 = __ldg(&b_gamma[c + 1]);
            float bt0 = __ldg(&b_beta[c]),  bt1 = __ldg(&b_beta[c + 1]);
            sh_gb[c * 132 + pxl]           = pack_bf16x2(acc2[nt][0] + bg0, acc2[nt + 8][0] + bt0);
            sh_gb[(c + 1) * 132 + pxl]     = pack_bf16x2(acc2[nt][1] + bg1, acc2[nt + 8][1] + bt1);
            sh_gb[c * 132 + pxl + 8]       = pack_bf16x2(acc2[nt][2] + bg0, acc2[nt + 8][2] + bt0);
            sh_gb[(c + 1) * 132 + pxl + 8] = pack_bf16x2(acc2[nt][3] + bg1, acc2[nt + 8][3] + bt1);
        }
    }
    __syncthreads();

    // ---- streaming epilogue: fully coalesced x read / out write, one channel per warp-iter ----
    {
        const float* xb = x + (((size_t)b * CN) << 16) + px0;
        float* ob = out + (((size_t)b * CN) << 16) + px0;
#pragma unroll
        for (int k = tid; k < 2048; k += 256) {
            int ch = k >> 5;           // warp covers one channel, 32 float4 = 128 px
            int pxq = k & 31;
            uint4 g = *reinterpret_cast<const uint4*>(&sh_gb[ch * 132 + 4 * pxq]);
            const float4 xv = __ldg(reinterpret_cast<const float4*>(xb + ((size_t)ch << 16)) + pxq);
            float mu = __ldg(&g_mu[b * CN + ch]);
            float rs = __ldg(&g_rstd[b * CN + ch]);
            float4 r;
            {
                __nv_bfloat162 p = *reinterpret_cast<__nv_bfloat162*>(&g.x);
                float xn = (xv.x - mu) * rs;
                r.x = xn * (1.f + __bfloat162float(p.x)) + __bfloat162float(p.y) + 0.1f * xv.x;
            }
            {
                __nv_bfloat162 p = *reinterpret_cast<__nv_bfloat162*>(&g.y);
                float xn = (xv.y - mu) * rs;
                r.y = xn * (1.f + __bfloat162float(p.x)) + __bfloat162float(p.y) + 0.1f * xv.y;
            }
            {
                __nv_bfloat162 p = *reinterpret_cast<__nv_bfloat162*>(&g.z);
                float xn = (xv.z - mu) * rs;
                r.z = xn * (1.f + __bfloat162float(p.x)) + __bfloat162float(p.y) + 0.1f * xv.z;
            }
            {
                __nv_bfloat162 p = *reinterpret_cast<__nv_bfloat162*>(&g.w);
                float xn = (xv.w - mu) * rs;
                r.w = xn * (1.f + __bfloat162float(p.x)) + __bfloat162float(p.y) + 0.1f * xv.w;
            }
            *(reinterpret_cast<float4*>(ob + ((size_t)ch << 16)) + pxq) = r;
        }
    }
}

extern "C" void kernel_launch(void* const* d_in, const int* in_sizes, int n_in,
                              void* d_out, int out_size) {
    (void)in_sizes; (void)n_in; (void)out_size;
    const float* x        = (const float*)d_in[0];
    const float* hm       = (const float*)d_in[1];
    const float* F        = (const float*)d_in[2];
    const float* w_shared = (const float*)d_in[3];
    const float* b_shared = (const float*)d_in[4];
    const float* w_gamma  = (const float*)d_in[5];
    const float* b_gamma  = (const float*)d_in[6];
    const float* w_beta   = (const float*)d_in[7];
    const float* b_beta   = (const float*)d_in[8];
    float* out = (float*)d_out;

    dim3 fgrid(8, 16, 68);   // z<64: FIR blocks; z>=64: stats blocks
    fir_kernel<<<fgrid, 256>>>(hm, F, w_shared, w_gamma, w_beta, x);
    dim3 ggrid(512, 8);
    gemm_kernel<<<ggrid, 256>>>(b_shared, b_gamma, b_beta, x, out);
}